// round 1
// baseline (speedup 1.0000x reference)
#include <cuda_runtime.h>
#include <math.h>

// Problem constants
#define NF      64          // fields
#define ND      32          // embedding dim
#define NPAIR   2016        // 64*63/2
#define SROW    36          // padded smem row stride (floats): float4-aligned, bank-stride 4

// Per-sample Gram + upper-triangle extraction.
// 2 samples per 128-thread CTA; each 64-thread group owns one sample.
// Each thread computes an 8x8 register tile of the 64x64 gram:
//   rows  i = ty*8 + ii        (ty = gt>>3)
//   cols  j = tx + 8*jj        (tx = gt&7)   -> conflict-free col-fragment LDS
__global__ __launch_bounds__(128, 1)
void gram_ut_kernel(const float* __restrict__ in, float* __restrict__ out, int nb)
{
    // Per-group buffer: first holds A (64 x SROW = 2304 floats), later reused
    // as full gram staging (64 x 64 = 4096 floats).
    __shared__ float sm[2][4096];

    const int grp = threadIdx.x >> 6;   // 0 or 1
    const int gt  = threadIdx.x & 63;   // thread id within group
    int b = blockIdx.x * 2 + grp;
    if (b >= nb) b = nb - 1;            // harmless duplicate work; keeps barriers uniform

    float* As = sm[grp];

    // ---------- Phase 1: load A[64][32] into padded smem ----------
    {
        const float4* src = (const float4*)(in + (size_t)b * (NF * ND));
        #pragma unroll
        for (int k = 0; k < 8; ++k) {
            int idx4 = gt + k * 64;              // 512 float4 total
            float4 v  = src[idx4];
            int f = idx4 >> 3;                   // row  (idx/32)
            int d = (idx4 & 7) * 4;              // col  (idx%32)
            *(float4*)&As[f * SROW + d] = v;     // 16B-aligned (SROW*4B = 144B)
        }
    }
    __syncthreads();

    // ---------- Phase 2: 8x8 register-tile gram ----------
    const int tx = gt & 7;
    const int ty = gt >> 3;

    float acc[8][8];
    #pragma unroll
    for (int ii = 0; ii < 8; ++ii)
        #pragma unroll
        for (int jj = 0; jj < 8; ++jj)
            acc[ii][jj] = 0.0f;

    #pragma unroll
    for (int d = 0; d < ND; d += 4) {
        float4 rv[8];
        #pragma unroll
        for (int ii = 0; ii < 8; ++ii)
            rv[ii] = *(const float4*)&As[(ty * 8 + ii) * SROW + d];

        #pragma unroll
        for (int jj = 0; jj < 8; ++jj) {
            float4 cv = *(const float4*)&As[(tx + 8 * jj) * SROW + d];
            #pragma unroll
            for (int ii = 0; ii < 8; ++ii) {
                acc[ii][jj] += rv[ii].x * cv.x;
                acc[ii][jj] += rv[ii].y * cv.y;
                acc[ii][jj] += rv[ii].z * cv.z;
                acc[ii][jj] += rv[ii].w * cv.w;
            }
        }
    }
    __syncthreads();   // everyone done reading A

    // ---------- Phase 3: stage full gram in smem (reuse buffer) ----------
    float* G = sm[grp];
    #pragma unroll
    for (int ii = 0; ii < 8; ++ii) {
        int i = ty * 8 + ii;
        #pragma unroll
        for (int jj = 0; jj < 8; ++jj) {
            int j = tx + 8 * jj;
            G[i * NF + j] = acc[ii][jj];   // quarter-warp lanes hit 8 consecutive banks
        }
    }
    __syncthreads();

    // ---------- Phase 4: coalesced float4 copy-out of upper triangle ----------
    // pair index p for (i,j), i<j:  p = i*63 - i*(i-1)/2 + (j-i-1)
    // row start: start(i) = (i*(127-i))/2     (exact in int)
    float* dst = out + (size_t)b * NPAIR;
    for (int p = gt * 4; p < NPAIR; p += 256) {
        // invert p -> i via exact discriminant (127-2i)^2 = 16129 - 8*start(i)
        int i = (int)((127.0f - sqrtf(16129.0f - 8.0f * (float)p)) * 0.5f);
        while (((i + 1) * (126 - i)) >> 1 <= p) ++i;   // fixups guard fp rounding
        while ((i * (127 - i)) >> 1 > p) --i;
        int j = i + 1 + (p - ((i * (127 - i)) >> 1));

        float4 o;
        o.x = G[i * NF + j]; if (++j == NF) { ++i; j = i + 1; }
        o.y = G[i * NF + j]; if (++j == NF) { ++i; j = i + 1; }
        o.z = G[i * NF + j]; if (++j == NF) { ++i; j = i + 1; }
        o.w = G[i * NF + j];
        *(float4*)&dst[p] = o;             // 16B-aligned: b*2016*4 and p*4 both %16==0
    }
}

extern "C" void kernel_launch(void* const* d_in, const int* in_sizes, int n_in,
                              void* d_out, int out_size)
{
    const float* in  = (const float*)d_in[0];
    float*       out = (float*)d_out;
    int nb = in_sizes[0] / (NF * ND);      // 16384
    int grid = (nb + 1) / 2;
    gram_ut_kernel<<<grid, 128>>>(in, out, nb);
}